// round 11
// baseline (speedup 1.0000x reference)
#include <cuda_runtime.h>
#include <math.h>

#define BB 16
#define AA 3
#define CC 80
#define HH 76
#define WW 76
#define TT 50
#define HWW 5776                 /* 76*76 */
#define NCELL (BB*AA*HWW)        /* 277248 */
#define NF4 (BB*AA*(HWW/4))      /* 69312 float4s of conf data */
#define NTGT (BB*TT)             /* 800 */
#define WPB 544                  /* bitmap words per batch (>=AA*HWW/32=541.5) */
#define NWORDS (BB*WPB)          /* 8704 */
#define NB 148
#define NT 256
#define NTHREADS (NB*NT)
#define NGWARPS (NTHREADS/32)

// ---------------- device scratch (written every launch; no init needed) ------
__device__ double g_part[NB][8];
__device__ unsigned int g_done;   // static-zero init; combiner resets to 0

struct Sh {
    int   cell[NTGT];
    int   cls[NTGT];
    float tx[NTGT], ty[NTGT], tw[NTGT], th[NTGT];
    unsigned int m0[NTGT], m1[NTGT], m2[NTGT];
    unsigned char win[NTGT];
    unsigned int bits[NWORDS];    // suppressed-cell bitmap (16 batches x 544 words)
    int nm;                       // winner count (== n_m)
    int nsup;                     // suppressed count
    float  sacc[8];
    double sdacc[8];
    unsigned int ticket;
};

// stable fast softplus, clipped at 100: == -clip(log(1-sigmoid(l)), -100)
__device__ __forceinline__ float sp(float l) {
    float v = fmaxf(l, 0.0f) + __logf(1.0f + __expf(-fabsf(l)));
    return fminf(v, 100.0f);
}

__global__ void __launch_bounds__(NT) k_fused(const float* __restrict__ inp,
                                              const float* __restrict__ tgt,
                                              float* __restrict__ out) {
    extern __shared__ char smem_raw[];
    Sh* sh = (Sh*)smem_raw;
    const int tid  = threadIdx.x;
    const int gtid = blockIdx.x * NT + tid;

    // ---- init shared ----
    for (int i = tid; i < NWORDS; i += NT) sh->bits[i] = 0u;
    if (tid < 8) { sh->sacc[tid] = 0.0f; sh->sdacc[tid] = 0.0; }
    if (tid == 0) { sh->nm = 0; sh->nsup = 0; }
    __syncthreads();

    const float aw[3] = {1.25f, 2.0f, 4.125f};     // ANCHORS / STRIDE (stride=8)
    const float ah[3] = {1.625f, 3.75f, 2.875f};

    // ---- build stage 1: per-target compute (every block, redundant+deterministic)
    for (int g = tid; g < NTGT; g += NT) {
        const float* p = tgt + (size_t)g * 5;
        float cls = p[0], x = p[1], y = p[2], w = p[3], h = p[4];
        bool valid = (cls + x + y + w + h) != 0.0f;
        float gx = x * WW, gy = y * HH, gw = w * WW, gh = h * HH;
        int gi = (int)gx, gj = (int)gy;
        bool inb = (gj >= 0) && (gj < HH) && (gi >= 0) && (gi < WW);
        int b = g / TT;
        float a1 = (gw + 1.0f) * (gh + 1.0f);
        float biou = -1.0f; int best = 0;
        #pragma unroll
        for (int a = 0; a < 3; a++) {
            float inter = fmaxf(fminf(gw, aw[a]) + 1.0f, 0.0f) *
                          fmaxf(fminf(gh, ah[a]) + 1.0f, 0.0f);
            float a2 = (aw[a] + 1.0f) * (ah[a] + 1.0f);
            float iou = inter / (a1 + a2 - inter + 1e-16f);
            if (iou > biou) { biou = iou; best = a; }
            if (valid && inb && iou > 0.5f) {
                int lc = (a*HH + gj)*WW + gi;
                atomicOr(&sh->bits[b*WPB + (lc >> 5)], 1u << (lc & 31));
            }
        }
        int cell = -1;
        if (valid && inb) {
            cell = ((b*AA + best)*HH + gj)*WW + gi;
            sh->tx[g] = gx - (float)gi;
            sh->ty[g] = gy - (float)gj;
            sh->tw[g] = __logf(gw / aw[best] + 1e-16f);
            sh->th[g] = __logf(gh / ah[best] + 1e-16f);
        }
        sh->cell[g] = cell;
        sh->cls[g]  = (int)cls;
    }
    __syncthreads();

    // ---- build stage 2: winner flags + class masks + counts ----
    for (int g = tid; g < NTGT; g += NT) {
        int cell = sh->cell[g];
        unsigned char w = 0;
        if (cell >= 0) {
            int b = g / TT, t = g - b * TT;
            bool winner = true;
            for (int t2 = t + 1; t2 < TT; t2++)
                if (sh->cell[b*TT + t2] == cell) { winner = false; break; }
            if (winner) {
                w = 1;
                unsigned int m0 = 0u, m1 = 0u, m2 = 0u;
                for (int t2 = 0; t2 <= t; t2++) {
                    if (sh->cell[b*TT + t2] == cell) {
                        int ci = sh->cls[b*TT + t2];
                        if (ci < 32)      m0 |= 1u << ci;
                        else if (ci < 64) m1 |= 1u << (ci - 32);
                        else              m2 |= 1u << (ci - 64);
                    }
                }
                sh->m0[g] = m0; sh->m1[g] = m1; sh->m2[g] = m2;
                atomicAdd(&sh->nm, 1);
            }
        }
        sh->win[g] = w;
    }
    // popcount bitmap -> nsup (redundant per block, needed only by combiner)
    {
        int c = 0;
        for (int w = tid; w < NWORDS; w += NT) c += __popc(sh->bits[w]);
        #pragma unroll
        for (int o = 16; o > 0; o >>= 1) c += __shfl_down_sync(0xffffffffu, c, o);
        if ((tid & 31) == 0 && c) atomicAdd(&sh->nsup, c);
    }
    __syncthreads();

    // ---- phases: global-grid partitioned work ----
    float acc[8];
    #pragma unroll
    for (int j = 0; j < 8; j++) acc[j] = 0.0f;

    // phase 1: bce(conf, 0) over ALL cells, float4 vectorized
    {
        const float4* inp4 = (const float4*)inp;
        for (int i = gtid; i < NF4; i += NTHREADS) {
            int plane = i / (HWW/4);
            int q     = i - plane * (HWW/4);
            int b = plane / AA, a = plane - b * AA;
            int base4 = (b*255 + a*85 + 4) * (HWW/4);
            float4 v = inp4[base4 + q];
            acc[6] += sp(v.x) + sp(v.y) + sp(v.z) + sp(v.w);
        }
    }

    // phase 2: subtract suppressed cells' conf terms (scan bitmap words)
    for (int w = gtid; w < NWORDS; w += NTHREADS) {
        unsigned int v = sh->bits[w];
        if (v) {
            int b = w / WPB;
            int base = (w - b * WPB) * 32;
            do {
                int bit = __ffs(v) - 1; v &= v - 1;
                int lc = base + bit;
                int a = lc / HWW, hw = lc - a * HWW;
                acc[7] += sp(inp[(size_t)(b*255 + a*85 + 4)*HWW + hw]);
            } while (v);
        }
    }

    // phase 3: masked-cell losses, one warp per winner target
    {
        int lane = tid & 31;
        int gw   = gtid >> 5;
        for (int g = gw; g < NTGT; g += NGWARPS) {
            if (!sh->win[g]) continue;
            int cell = sh->cell[g];
            int b = cell / (AA*HWW);
            int r = cell - b*(AA*HWW);
            int a = r / HWW;
            int hw = r - a*HWW;
            const float* base = inp + (size_t)(b*255 + a*85)*HWW + hw;
            unsigned int m0 = sh->m0[g], m1 = sh->m1[g], m2 = sh->m2[g];
            #pragma unroll
            for (int k = 0; k < 3; k++) {
                int ch = lane + 32*k;
                if (ch < 85) {
                    float l = base[(size_t)ch * HWW];
                    if (ch >= 5) {
                        int c = ch - 5;
                        unsigned int mm = (c < 32) ? m0 : ((c < 64) ? m1 : m2);
                        float tt = ((mm >> (c & 31)) & 1u) ? 1.0f : 0.0f;
                        acc[5] += sp(l) - tt * l;
                    } else if (ch == 0) {
                        acc[0] += sp(l) - sh->tx[g] * l;
                    } else if (ch == 1) {
                        acc[1] += sp(l) - sh->ty[g] * l;
                    } else if (ch == 2) {
                        float d = l - sh->tw[g]; acc[2] += d * d;
                    } else if (ch == 3) {
                        float d = l - sh->th[g]; acc[3] += d * d;
                    } else { // ch == 4: bce(conf, 1) = sp(-l)
                        acc[4] += sp(-l);
                    }
                }
            }
        }
    }

    // ---- block reduction: warp shuffle -> shared f32 atomics ----
    #pragma unroll
    for (int j = 0; j < 8; j++) {
        float v = acc[j];
        #pragma unroll
        for (int o = 16; o > 0; o >>= 1) v += __shfl_down_sync(0xffffffffu, v, o);
        if ((tid & 31) == 0 && v != 0.0f) atomicAdd(&sh->sacc[j], v);
    }
    __syncthreads();

    // write per-block partials (every slot written every launch; no init needed)
    if (tid < 8) g_part[blockIdx.x][tid] = (double)sh->sacc[tid];
    __threadfence();
    __syncthreads();
    if (tid == 0) sh->ticket = atomicAdd(&g_done, 1u);
    __syncthreads();

    // ---- last block: parallel slot sum + final combine ----
    if (sh->ticket == NB - 1) {
        double part[8];
        #pragma unroll
        for (int j = 0; j < 8; j++) part[j] = 0.0;
        if (tid < NB) {
            #pragma unroll
            for (int j = 0; j < 8; j++) part[j] = g_part[tid][j];
        }
        #pragma unroll
        for (int j = 0; j < 8; j++) {
            double v = part[j];
            #pragma unroll
            for (int o = 16; o > 0; o >>= 1) v += __shfl_down_sync(0xffffffffu, v, o);
            if ((tid & 31) == 0 && v != 0.0) atomicAdd(&sh->sdacc[j], v);
        }
        __syncthreads();
        if (tid == 0) {
            double A0 = sh->sdacc[0], A1 = sh->sdacc[1], A2 = sh->sdacc[2], A3 = sh->sdacc[3];
            double A4 = sh->sdacc[4], A5 = sh->sdacc[5], A6 = sh->sdacc[6], A7 = sh->sdacc[7];
            double Nd   = (double)NCELL;
            double n_m  = (double)sh->nm;
            double n_nm = (double)(NCELL - sh->nsup);
            double lx = (A0 / Nd) / n_m;
            double ly = (A1 / Nd) / n_m;
            double lw = (A2 / Nd) / n_m;
            double lh = (A3 / Nd) / n_m;
            double lconf = (A4 / Nd) / n_m + 0.5 * ((A6 - A7) / Nd) / n_nm;
            double lcls  = A5 / (n_m * (double)CC) / n_m;
            double loss  = 2.5 * (lx + ly) + 2.5 * (lw + lh) + lconf + lcls;
            out[0] = (float)loss;
            out[1] = (float)lx;    out[2] = (float)ly;
            out[3] = (float)lw;    out[4] = (float)lh;
            out[5] = (float)lconf; out[6] = (float)lcls;
            g_done = 0u;           // reset for next graph replay
        }
    }
}

// ---------------- launch ----------------
extern "C" void kernel_launch(void* const* d_in, const int* in_sizes, int n_in,
                              void* d_out, int out_size) {
    const float* inp;
    const float* tgt;
    if (in_sizes[0] > in_sizes[1]) { inp = (const float*)d_in[0]; tgt = (const float*)d_in[1]; }
    else                           { inp = (const float*)d_in[1]; tgt = (const float*)d_in[0]; }
    float* out = (float*)d_out;

    cudaFuncSetAttribute(k_fused, cudaFuncAttributeMaxDynamicSharedMemorySize,
                         (int)sizeof(Sh));
    k_fused<<<NB, NT, sizeof(Sh)>>>(inp, tgt, out);
}

// round 15
// speedup vs baseline: 4.4685x; 4.4685x over previous
#include <cuda_runtime.h>
#include <math.h>

#define BB 16
#define AA 3
#define CC 80
#define HH 76
#define WW 76
#define TT 50
#define HWW 5776                 /* 76*76 */
#define NCELL (BB*AA*HWW)        /* 277248 */
#define NF4 (BB*AA*(HWW/4))      /* 69312 float4s of conf data */
#define NTGT (BB*TT)             /* 800 */
#define NB 592                   /* 4 blocks per SM */
#define NT 256
#define NTHREADS (NB*NT)
#define NGWARPS (NTHREADS/32)

// ---------------- device scratch ----------------
__device__ int g_nentries, g_nsup;
__device__ int g_ecell[NTGT];
__device__ float g_etx[NTGT], g_ety[NTGT], g_etw[NTGT], g_eth[NTGT];
__device__ unsigned int g_ecls[NTGT][3];
__device__ int g_sup[NTGT*AA];
__device__ double g_part[NB][8]; // every slot written each launch; no init needed
__device__ unsigned int g_done;  // reset by k_build each launch

// stable fast softplus, clipped at 100: == -clip(log(1-sigmoid(l)), -100)
__device__ __forceinline__ float sp(float l) {
    float v = fmaxf(l, 0.0f) + __logf(1.0f + __expf(-fabsf(l)));
    return fminf(v, 100.0f);
}

// ---------------- kernel 1: parallel target build (proven R9 version) --------
__global__ void __launch_bounds__(832) k_build(const float* __restrict__ tgt) {
    __shared__ int s_cell[NTGT];
    __shared__ int s_cls[NTGT];
    __shared__ unsigned int bits[BB*544];   // suppressed-cell bitmap per batch
    const int tid = threadIdx.x;

    for (int i = tid; i < BB*544; i += blockDim.x) bits[i] = 0u;
    if (tid == 0) { g_nentries = 0; g_nsup = 0; g_done = 0u; }
    __syncthreads();

    const float aw[3] = {1.25f, 2.0f, 4.125f};     // ANCHORS / STRIDE (stride=8)
    const float ah[3] = {1.625f, 3.75f, 2.875f};

    int cell = -1;
    float tx = 0.f, ty = 0.f, tw = 0.f, th = 0.f;
    int b = tid / TT, t = tid - b * TT;

    if (tid < NTGT) {
        const float* p = tgt + (size_t)tid * 5;
        float cls = p[0], x = p[1], y = p[2], w = p[3], h = p[4];
        bool valid = (cls + x + y + w + h) != 0.0f;
        float gx = x * WW, gy = y * HH, gw = w * WW, gh = h * HH;
        int gi = (int)gx, gj = (int)gy;
        bool inb = (gj >= 0) && (gj < HH) && (gi >= 0) && (gi < WW);
        float a1 = (gw + 1.0f) * (gh + 1.0f);
        float biou = -1.0f; int best = 0;
        #pragma unroll
        for (int a = 0; a < 3; a++) {
            float inter = fmaxf(fminf(gw, aw[a]) + 1.0f, 0.0f) *
                          fmaxf(fminf(gh, ah[a]) + 1.0f, 0.0f);
            float a2 = (aw[a] + 1.0f) * (ah[a] + 1.0f);
            float iou = inter / (a1 + a2 - inter + 1e-16f);
            if (iou > biou) { biou = iou; best = a; }
            if (valid && inb && iou > 0.5f) {
                int lc = (a*HH + gj)*WW + gi;
                unsigned int bt = 1u << (lc & 31);
                unsigned int old = atomicOr(&bits[b*544 + (lc >> 5)], bt);
                if (!(old & bt)) {                    // first to suppress this cell
                    int so = atomicAdd(&g_nsup, 1);
                    g_sup[so] = b*AA*HWW + lc;
                }
            }
        }
        if (valid && inb) {
            cell = ((b*AA + best)*HH + gj)*WW + gi;
            tx = gx - (float)gi; ty = gy - (float)gj;
            tw = __logf(gw / aw[best] + 1e-16f);
            th = __logf(gh / ah[best] + 1e-16f);
        }
        s_cell[tid] = cell;
        s_cls[tid]  = (int)cls;
    }
    __syncthreads();

    if (tid < NTGT && cell >= 0) {
        // last-writer-wins: am I the latest target in my batch mapping to this cell?
        bool winner = true;
        for (int t2 = t + 1; t2 < TT; t2++)
            if (s_cell[b*TT + t2] == cell) { winner = false; break; }
        if (winner) {
            unsigned int m0 = 0u, m1 = 0u, m2 = 0u;
            for (int t2 = 0; t2 <= t; t2++) {          // class bits OR over ALL writers
                if (s_cell[b*TT + t2] == cell) {
                    int ci = s_cls[b*TT + t2];
                    if (ci < 32)      m0 |= 1u << ci;
                    else if (ci < 64) m1 |= 1u << (ci - 32);
                    else              m2 |= 1u << (ci - 64);
                }
            }
            int off = atomicAdd(&g_nentries, 1);
            g_ecell[off] = cell;
            g_etx[off] = tx; g_ety[off] = ty;
            g_etw[off] = tw; g_eth[off] = th;
            g_ecls[off][0] = m0; g_ecls[off][1] = m1; g_ecls[off][2] = m2;
        }
    }
}

// ---------------- kernel 2: main losses (<=1 item/thread, max MLP) ----------
__global__ void __launch_bounds__(NT) k_main(const float* __restrict__ inp,
                                             float* __restrict__ out) {
    float acc[8];
    #pragma unroll
    for (int j = 0; j < 8; j++) acc[j] = 0.0f;

    const int tid  = threadIdx.x;
    const int gtid = blockIdx.x * NT + tid;

    // ---- phase 1: bce(conf, 0) over ALL cells, one float4 per thread ----
    if (gtid < NF4) {
        int plane = gtid / (HWW/4);
        int q     = gtid - plane * (HWW/4);
        int b = plane / AA, a = plane - b * AA;
        int base4 = (b*255 + a*85 + 4) * (HWW/4);
        float4 v = ((const float4*)inp)[base4 + q];
        acc[6] = sp(v.x) + sp(v.y) + sp(v.z) + sp(v.w);
    }

    // ---- phase 2: subtract suppressed cells' conf terms (<=1 per thread) ----
    if (gtid < g_nsup) {
        int cell = g_sup[gtid];
        int b = cell / (AA*HWW);
        int r = cell - b*(AA*HWW);
        int a = r / HWW;
        int hw = r - a*HWW;
        acc[7] = sp(inp[(size_t)(b*255 + a*85 + 4)*HWW + hw]);
    }

    // ---- phase 3: masked-cell losses, one warp per entry (<=1 per warp) ----
    {
        int lane = tid & 31;
        int wid  = gtid >> 5;
        if (wid < g_nentries) {
            int e = wid;
            int cell = g_ecell[e];
            int b = cell / (AA*HWW);
            int r = cell - b*(AA*HWW);
            int a = r / HWW;
            int hw = r - a*HWW;
            const float* base = inp + (size_t)(b*255 + a*85)*HWW + hw;
            unsigned int m0 = g_ecls[e][0], m1 = g_ecls[e][1], m2 = g_ecls[e][2];
            #pragma unroll
            for (int k = 0; k < 3; k++) {
                int ch = lane + 32*k;
                if (ch < 85) {
                    float l = base[(size_t)ch * HWW];
                    if (ch >= 5) {
                        int c = ch - 5;
                        unsigned int mm = (c < 32) ? m0 : ((c < 64) ? m1 : m2);
                        float tt = ((mm >> (c & 31)) & 1u) ? 1.0f : 0.0f;
                        acc[5] += sp(l) - tt * l;
                    } else if (ch == 0) {
                        acc[0] = sp(l) - g_etx[e] * l;
                    } else if (ch == 1) {
                        acc[1] = sp(l) - g_ety[e] * l;
                    } else if (ch == 2) {
                        float d = l - g_etw[e]; acc[2] = d * d;
                    } else if (ch == 3) {
                        float d = l - g_eth[e]; acc[3] = d * d;
                    } else { // ch == 4: bce(conf, 1) = sp(-l)
                        acc[4] = sp(-l);
                    }
                }
            }
        }
    }

    // ---- block reduction: warp shuffle (f32) -> shared atomics -> slot write --
    __shared__ float sacc[8];
    __shared__ unsigned int ticket;
    if (tid < 8) sacc[tid] = 0.0f;
    __syncthreads();
    #pragma unroll
    for (int j = 0; j < 8; j++) {
        float v = acc[j];
        #pragma unroll
        for (int o = 16; o > 0; o >>= 1) v += __shfl_down_sync(0xffffffffu, v, o);
        if ((tid & 31) == 0 && v != 0.0f) atomicAdd(&sacc[j], v);
    }
    __syncthreads();
    if (tid < 8) g_part[blockIdx.x][tid] = (double)sacc[tid];
    __threadfence();
    __syncthreads();
    if (tid == 0) ticket = atomicAdd(&g_done, 1u);
    __syncthreads();

    // ---- last block: sum 592 slots + final combine ----
    if (ticket == NB - 1) {
        double part[8];
        #pragma unroll
        for (int j = 0; j < 8; j++) part[j] = 0.0;
        for (int s = tid; s < NB; s += NT) {
            #pragma unroll
            for (int j = 0; j < 8; j++) part[j] += g_part[s][j];
        }
        __shared__ double sd[8];
        if (tid < 8) sd[tid] = 0.0;
        __syncthreads();
        #pragma unroll
        for (int j = 0; j < 8; j++) {
            double v = part[j];
            #pragma unroll
            for (int o = 16; o > 0; o >>= 1) v += __shfl_down_sync(0xffffffffu, v, o);
            if ((tid & 31) == 0 && v != 0.0) atomicAdd(&sd[j], v);
        }
        __syncthreads();
        if (tid == 0) {
            double A0 = sd[0], A1 = sd[1], A2 = sd[2], A3 = sd[3];
            double A4 = sd[4], A5 = sd[5], A6 = sd[6], A7 = sd[7];
            double Nd   = (double)NCELL;
            double n_m  = (double)g_nentries;
            double n_nm = (double)(NCELL - g_nsup);
            double lx = (A0 / Nd) / n_m;
            double ly = (A1 / Nd) / n_m;
            double lw = (A2 / Nd) / n_m;
            double lh = (A3 / Nd) / n_m;
            double lconf = (A4 / Nd) / n_m + 0.5 * ((A6 - A7) / Nd) / n_nm;
            double lcls  = A5 / (n_m * (double)CC) / n_m;
            double loss  = 2.5 * (lx + ly) + 2.5 * (lw + lh) + lconf + lcls;
            out[0] = (float)loss;
            out[1] = (float)lx;    out[2] = (float)ly;
            out[3] = (float)lw;    out[4] = (float)lh;
            out[5] = (float)lconf; out[6] = (float)lcls;
        }
    }
}

// ---------------- launch ----------------
extern "C" void kernel_launch(void* const* d_in, const int* in_sizes, int n_in,
                              void* d_out, int out_size) {
    const float* inp;
    const float* tgt;
    if (in_sizes[0] > in_sizes[1]) { inp = (const float*)d_in[0]; tgt = (const float*)d_in[1]; }
    else                           { inp = (const float*)d_in[1]; tgt = (const float*)d_in[0]; }
    float* out = (float*)d_out;

    k_build<<<1, 832>>>(tgt);
    k_main <<<NB, NT>>>(inp, out);
}